// round 11
// baseline (speedup 1.0000x reference)
#include <cuda_runtime.h>

#define NXg 1024
#define NYg 85
#define N_AMPS 1500
#define NCH 375          // N_AMPS / 4 chunks
#define WCHUNKS 6        // warp-uniform window: 6 float4 chunks = 24 amps
#define NBLK 136         // 136 * 640 == 1024*85 == 87040 exactly
#define NTHR 640

__device__ __forceinline__ float ex2f(float x) {
    float r;
    asm("ex2.approx.ftz.f32 %0, %1;" : "=f"(r) : "f"(x));
    return r;
}

__global__ __launch_bounds__(NTHR)
void echellogram_kernel(
    const int*   __restrict__ index_p,
    const float* __restrict__ bkg_p,
    const float* __restrict__ s_coeffs,
    const float* __restrict__ amps,
    const float* __restrict__ smooth_p,
    const float* __restrict__ lam_coeffs,
    const float* __restrict__ p_coeffs,
    const float* __restrict__ src_amps,
    const float* __restrict__ fiducial,
    const float* __restrict__ lam_vector,
    float*       __restrict__ out)
{
    const float SIGMA        = 0.42f;
    const float INV_SIGMA    = 1.0f / 0.42f;
    const float SLIT         = 12.0f;
    const float INV_SQRT_2PI = 0.3989422804014327f;
    const float LOG_SQRT_2PI = 0.9189385332046727f;
    const float LOG2E        = 1.4426950408889634f;

    int i = blockIdx.x * NTHR + threadIdx.x;   // exact: 136*640 = 87040 pixels
    int x = i / NYg;                           // magic-multiply division
    int y = i - x * NYg;
    float xf = (float)x;
    float yf = (float)y;

    // warp endpoint pixels (computable before any load returns)
    int iw0 = i & ~31;
    int iw1 = iw0 + 31;
    int xa = iw0 / NYg, ya = iw0 - xa * NYg;
    int xb = iw1 / NYg, yb = iw1 - xb * NYg;

    // ---- batch 1: ONLY the loads gating the window address ----
    float c0 = lam_coeffs[0], c1 = lam_coeffs[1], c2 = lam_coeffs[2], c3 = lam_coeffs[3];
    float f0 = fiducial[0],   f1 = fiducial[1];
    float lam0_v = lam_vector[0];
    float lamN_v = lam_vector[N_AMPS - 1];
    // ---- batch 2: everything else (overlaps the window-load L2 trip) ----
    int   idx        = index_p[0];
    float pcA0 = p_coeffs[0];
    float pcA1 = p_coeffs[1];
    float pcB0 = p_coeffs[2];
    float pcB1 = p_coeffs[3];
    float bkg        = bkg_p[0];
    float smoothness = smooth_p[0];
    float s0 = s_coeffs[0], s1 = s_coeffs[1], s2 = s_coeffs[2];

    // --- wavelength surface (critical path) ---
    float cx1 = f1 * (1.0f + c1 * 0.01f) * 512.0f;
    float cx2 = 1.0f + c2;
    float base = f0 + c0;

    #define LAM_AT(XF, YF)                                                         \
        (base + cx1 * (((XF) - 512.0f) * (1.0f / 512.0f))                           \
              + cx2 * (2.0f * (((XF) - 512.0f) * (1.0f / 512.0f))                   \
                            * (((XF) - 512.0f) * (1.0f / 512.0f)) - 1.0f)           \
              + c3 * (((YF) - 42.5f) * (1.0f / 42.5f)))

    float lam = LAM_AT(xf, yf);

    // --- analytic warp min/max of lam (no REDUX): lam affine in y per column ---
    float lamA = LAM_AT((float)xa, (float)ya);
    float lamB = LAM_AT((float)xb, (float)yb);
    float lmin = fminf(lamA, lamB);
    float lmax = fmaxf(lamA, lamB);
    if (xb != xa) {                      // warp crosses one x boundary
        float lamC = LAM_AT((float)xa, (float)(NYg - 1));
        float lamD = LAM_AT((float)xb, 0.0f);
        lmin = fminf(lmin, fminf(lamC, lamD));
        lmax = fmaxf(lmax, fmaxf(lamC, lamD));
    }

    float dlam = (lamN_v - lam0_v) * (1.0f / (float)(N_AMPS - 1));
    int k0, k1;
    if (fabsf(dlam) > 1e-20f) {
        float inv_dlam = __fdividef(1.0f, dlam);
        float hw = 3.8f * SIGMA * fabsf(inv_dlam);   // 3.8-sigma half-window
        float tcl = (lmin - lam0_v) * inv_dlam;
        float tch = (lmax - lam0_v) * inv_dlam;
        float tmin = fminf(tcl, tch);
        float tmax = fmaxf(tcl, tch);
        int lo = max(0,          (int)floorf(tmin - hw));
        int hi = min(N_AMPS - 1, (int)ceilf (tmax + hw));
        k0 = lo >> 2;
        k1 = hi >> 2;
    } else {
        k0 = 0; k1 = NCH - 1;                        // degenerate: sum everything
    }
    k0 = min(k0, NCH - WCHUNKS);

    const float4* __restrict__ lam4 = (const float4*)lam_vector;
    const float4* __restrict__ amp4 = (const float4*)amps;
    const float4* __restrict__ srv4 = (const float4*)src_amps;

    // p = 2^(-(B*lam - B*lv)^2),  B = inv_sigma * sqrt(0.5*log2(e))
    const float B    = INV_SIGMA * 0.8493218002880191f;
    const float negB = -B;
    const float lamBs = lam * B;

    // --- epilogue math FIRST: independent of window loads -> fills their shadow ---
    float pc0 = (idx == 0) ? pcA0 : pcB0;
    float pc1 = (idx == 0) ? pcA1 : pcB1;
    float ss  = s1 * (yf - s0 - s2 * xf);

    float inv_beta = ex2f(-smoothness * LOG2E);
    float ea = ex2f(-(ss * inv_beta) * LOG2E);
    float eb = ex2f(-((SLIT - ss) * inv_beta) * LOG2E);
    float emask = __fdividef(1.0f, (1.0f + ea) * (1.0f + eb));

    float inv_sig_s = ex2f(-pc1 * LOG2E);      // 1/exp(pc1)
    float u = (ss - pc0) * inv_sig_s;
    float src_prof = ex2f(fmaf(-0.5f * u, u, -pc1 - LOG_SQRT_2PI) * LOG2E);

    // --- windowed Gaussian-comb reduction ---
    float sky0 = 0.0f, sky1 = 0.0f, src0 = 0.0f, src1 = 0.0f;
    #pragma unroll
    for (int k = 0; k < WCHUNKS; ++k) {
        int a = k0 + k;                 // warp-uniform -> broadcast LDG.128
        float4 lv = lam4[a];
        float4 av = amp4[a];
        float4 sv = srv4[a];
        float z0 = fmaf(lv.x, negB, lamBs);
        float z1 = fmaf(lv.y, negB, lamBs);
        float z2 = fmaf(lv.z, negB, lamBs);
        float z3 = fmaf(lv.w, negB, lamBs);
        float p0 = ex2f(z0 * (-z0));
        float p1 = ex2f(z1 * (-z1));
        float p2 = ex2f(z2 * (-z2));
        float p3 = ex2f(z3 * (-z3));
        sky0 = fmaf(av.x, p0, sky0);
        sky1 = fmaf(av.y, p1, sky1);
        sky0 = fmaf(av.z, p2, sky0);
        sky1 = fmaf(av.w, p3, sky1);
        src0 = fmaf(sv.x, p0, src0);
        src1 = fmaf(sv.y, p1, src1);
        src0 = fmaf(sv.z, p2, src0);
        src1 = fmaf(sv.w, p3, src1);
    }
    // generic tail: covers any window wider than WCHUNKS (safety net)
    for (int a = k0 + WCHUNKS; a <= k1; ++a) {
        float4 lv = lam4[a];
        float4 av = amp4[a];
        float4 sv = srv4[a];
        float z0 = fmaf(lv.x, negB, lamBs);
        float z1 = fmaf(lv.y, negB, lamBs);
        float z2 = fmaf(lv.z, negB, lamBs);
        float z3 = fmaf(lv.w, negB, lamBs);
        float p0 = ex2f(z0 * (-z0));
        float p1 = ex2f(z1 * (-z1));
        float p2 = ex2f(z2 * (-z2));
        float p3 = ex2f(z3 * (-z3));
        sky0 = fmaf(av.x, p0, sky0);
        sky1 = fmaf(av.y, p1, sky1);
        sky0 = fmaf(av.z, p2, sky0);
        sky1 = fmaf(av.w, p3, sky1);
        src0 = fmaf(sv.x, p0, src0);
        src1 = fmaf(sv.y, p1, src1);
        src0 = fmaf(sv.z, p2, src0);
        src1 = fmaf(sv.w, p3, src1);
    }

    float norm = INV_SQRT_2PI * INV_SIGMA;
    float sky = (sky0 + sky1) * norm;
    float src = (src0 + src1) * norm;

    out[i] = emask * sky + src_prof * src + bkg;
}

extern "C" void kernel_launch(void* const* d_in, const int* in_sizes, int n_in,
                              void* d_out, int out_size) {
    (void)in_sizes; (void)n_in; (void)out_size;
    const int*   index_p    = (const int*)  d_in[0];
    const float* bkg_p      = (const float*)d_in[1];
    const float* s_coeffs   = (const float*)d_in[2];
    const float* amps       = (const float*)d_in[3];
    const float* smooth_p   = (const float*)d_in[4];
    const float* lam_coeffs = (const float*)d_in[5];
    const float* p_coeffs   = (const float*)d_in[6];
    const float* src_amps   = (const float*)d_in[7];
    const float* fiducial   = (const float*)d_in[8];
    const float* lam_vector = (const float*)d_in[9];
    float* out = (float*)d_out;

    echellogram_kernel<<<NBLK, NTHR>>>(    // 136 x 640 = 87040 pixels exactly
        index_p, bkg_p, s_coeffs, amps, smooth_p, lam_coeffs,
        p_coeffs, src_amps, fiducial, lam_vector, out);
}